// round 12
// baseline (speedup 1.0000x reference)
#include <cuda_runtime.h>
#include <math.h>

#define NP 4096
#define NI 256
#define NH 64
#define NA 32

#define NBINS 256
#define TROWS (NBINS + 1)        // rows 0..256
#define PADOFF (TROWS * 128)     // byte offset of zero row

#define WPC 14                   // persons per CTA (2 per warp)
#define NWARP 7
#define NTHR (NWARP * 32)        // 224
#define CLUSTER 8
#define GRID 296                 // 37 clusters of 8; covers 296*14=4144 >= 4096

// Output layout (flattened tuple, fp32)
#define O_AMU  (NP * NI)
#define O_ALV  (O_AMU + NP * NA)
#define O_IMU  (O_ALV + NP * NA)
#define O_ILV  (O_IMU + NI)

// ---- staged block (word offsets) ----
#define TAB_WORDS ((TROWS + 1) * 32)      // 8256 (incl zero row)
#define WSTRIDE 68
#define W3A_OFF TAB_WORDS
#define W3B_OFF (W3A_OFF + 32 * WSTRIDE)
#define W4A_OFF (W3B_OFF + 32 * WSTRIDE)
#define W4B_OFF (W4A_OFF + 32 * WSTRIDE)
#define IFE_OFF (W4B_OFF + 32 * WSTRIDE)
#define STAGED_WORDS (IFE_OFF + NI)       // 17216
#define STAGED_BYTES (STAGED_WORDS * 4)   // 68864
#define SLICE_BYTES (STAGED_BYTES / CLUSTER)   // 8608 (16B aligned)
#define SLICE_WORDS (STAGED_WORDS / CLUSTER)   // 2152

// smem: staged | cmp[WPC][256] | buf[WPC][64] | mbar   (~85 KB -> 2 CTAs/SM)
#define CMP_OFF  STAGED_WORDS
#define BUF_OFF  (CMP_OFF + WPC * NI)
#define MBAR_OFF (BUF_OFF + WPC * NH)
#define SMEM_BYTES (MBAR_OFF * 4 + 16)

__device__ __align__(16) float g_staged[STAGED_WORDS];

__device__ __forceinline__ float elu_ref(float x) {
    return x > 0.0f ? x : expm1f(x);
}
__device__ __forceinline__ float elu_fast(float x) {
    return x > 0.0f ? x : (__expf(x) - 1.0f);
}
__device__ __forceinline__ void addbf2(unsigned long long& acc, unsigned int w) {
    asm("{\n\t"
        ".reg .b32 lo, hi;\n\t"
        ".reg .b64 t;\n\t"
        "shl.b32 lo, %1, 16;\n\t"
        "and.b32 hi, %1, 0xffff0000;\n\t"
        "mov.b64 t, {lo, hi};\n\t"
        "add.rn.f32x2 %0, %0, t;\n\t"
        "}" : "+l"(acc) : "r"(w));
}
__device__ __forceinline__ void fma2(unsigned long long& acc,
                                     unsigned long long a, unsigned long long b) {
    asm("fma.rn.f32x2 %0, %1, %2, %0;" : "+l"(acc) : "l"(a), "l"(b));
}
__device__ __forceinline__ void mbar_wait(unsigned int mbar) {
    unsigned int done;
    asm volatile(
        "{\n\t.reg .pred p;\n\t"
        "mbarrier.try_wait.parity.acquire.cta.shared::cta.b64 p, [%1], 0;\n\t"
        "selp.b32 %0, 1, 0, p;\n\t}"
        : "=r"(done) : "r"(mbar) : "memory");
    while (!done) {
        asm volatile(
            "{\n\t.reg .pred p;\n\t"
            "mbarrier.try_wait.parity.acquire.cta.shared::cta.b64 p, [%1], 0, 0x989680;\n\t"
            "selp.b32 %0, 1, 0, p;\n\t}"
            : "=r"(done) : "r"(mbar) : "memory");
    }
}
#define CLUSTER_SYNC() do { \
    asm volatile("barrier.cluster.arrive.aligned;" ::: "memory"); \
    asm volatile("barrier.cluster.wait.aligned;" ::: "memory"); \
} while (0)

// ---------------------------------------------------------------------------
// Kernel 1: WIDE builder — one table row per 64-thread block.
// ---------------------------------------------------------------------------
__global__ void build_all_kernel(const float* __restrict__ w1,
                                 const float* __restrict__ b1,
                                 const float* __restrict__ w2,
                                 const float* __restrict__ b2,
                                 const float* __restrict__ w3,
                                 const float* __restrict__ w4,
                                 const int*   __restrict__ item_index,
                                 const float* __restrict__ eps_item,
                                 const float* __restrict__ mu_table,
                                 const float* __restrict__ logvar_table,
                                 float* __restrict__ out) {
    int blk = blockIdx.x;
    int j = threadIdx.x;   // 0..63

    if (blk < TROWS) {
        __shared__ float h1[NH];
        float x = (float)blk * (1.0f / (float)NBINS);
        h1[j] = elu_ref(fmaf(w1[j], x, b1[j]));
        __syncthreads();
        float z = b2[j];
#pragma unroll 8
        for (int k = 0; k < NH; k++)
            z = fmaf(h1[k], w2[k * NH + j], z);
        z = elu_ref(z);
        float zo = __shfl_xor_sync(0xffffffffu, z, 1);
        if ((j & 1) == 0) {
            unsigned int u;
            asm("cvt.rn.bf16x2.f32 %0, %1, %2;" : "=r"(u) : "f"(zo), "f"(z));
            g_staged[blk * 32 + (j >> 1)] = __uint_as_float(u);
        }
    } else if (blk < TROWS + 4) {
        int arr = blk - TROWS;                 // 0:w3A 1:w3B 2:w4A 3:w4B
        const float* src = (arr < 2) ? w3 : w4;
        int parity = arr & 1;
        int dst = W3A_OFF + arr * 32 * WSTRIDE;
        for (int i = j; i < 32 * NH; i += 64) {
            int k = i >> 5, l = i & 31;
            g_staged[dst + l * WSTRIDE + k] = src[k * NH + 2 * l + parity];
        }
    } else {
        if (j < 32) g_staged[TROWS * 32 + j] = 0.0f;   // zero row
        for (int i = j; i < NI; i += 64) {
            int idx = item_index[i];
            float imu = mu_table[idx];
            float ilv = logvar_table[idx];
            g_staged[IFE_OFF + i] = fmaf(eps_item[i], __expf(0.5f * ilv), imu);
            out[O_IMU + i] = imu;
            out[O_ILV + i] = ilv;
        }
    }
}

// ---------------------------------------------------------------------------
// Kernel 2: 7 warps, 2 persons/warp, 2 CTAs/SM. Multicast TMA prologue:
// 8-CTA cluster, each rank loads 1/8 slice and multicasts to all.
// ---------------------------------------------------------------------------
__global__ __launch_bounds__(NTHR, 2)
void vibo_main_kernel(const float* __restrict__ response,
                      const int*   __restrict__ mask,
                      const float* __restrict__ eps_ability,
                      const float* __restrict__ b3,
                      const float* __restrict__ b4,
                      float* __restrict__ out) {
    extern __shared__ float sm[];
    const int tid = threadIdx.x;
    const int wid  = tid >> 5;
    const int lane = tid & 31;
    const int p0 = blockIdx.x * WPC + wid * 2;
    const int p1 = p0 + 1;
    const unsigned int rank = blockIdx.x & (CLUSTER - 1);

    unsigned int smb;
    asm("{ .reg .u64 t; cvta.to.shared.u64 t, %1; cvt.u32.u64 %0, t; }"
        : "=r"(smb) : "l"(sm));
    const unsigned int bar1 = smb + MBAR_OFF * 4;

    // ---- early gmem loads (both persons) ----
    float4 r0a, r1a, r0b, r1b; int4 m0a, m1a, m0b, m1b;
    if (p0 < NP) {
        const float4* rp = (const float4*)(response + p0 * NI);
        const int4*   mp = (const int4*)(mask + p0 * NI);
        r0a = rp[lane * 2]; r1a = rp[lane * 2 + 1];
        m0a = mp[lane * 2]; m1a = mp[lane * 2 + 1];
    }
    if (p1 < NP) {
        const float4* rp = (const float4*)(response + p1 * NI);
        const int4*   mp = (const int4*)(mask + p1 * NI);
        r0b = rp[lane * 2]; r1b = rp[lane * 2 + 1];
        m0b = mp[lane * 2]; m1b = mp[lane * 2 + 1];
    }

    if (tid == 0) {
        asm volatile("mbarrier.init.shared.b64 [%0], 1;" :: "r"(bar1) : "memory");
    }
    __syncthreads();
    // all cluster CTAs' mbarriers must be initialized before any multicast
    CLUSTER_SYNC();

    if (tid == 0) {
        asm volatile("mbarrier.arrive.expect_tx.shared.b64 _, [%0], %1;"
                     :: "r"(bar1), "r"((unsigned)STAGED_BYTES) : "memory");
        // cooperative slice: rank r loads slice r, multicast to all 8 CTAs
        asm volatile(
            "cp.async.bulk.shared::cluster.global.mbarrier::complete_tx::bytes.multicast::cluster "
            "[%0], [%1], %2, [%3], %4;"
            :: "r"(smb + rank * SLICE_BYTES),
               "l"((const void*)(g_staged + rank * SLICE_WORDS)),
               "r"((unsigned)SLICE_BYTES), "r"(bar1),
               "h"((unsigned short)((1u << CLUSTER) - 1u))
            : "memory");
    }

    // ---- compaction for both persons (overlaps TMA) ----
    unsigned int* cmp0 = (unsigned int*)(sm + CMP_OFF) + (wid * 2) * NI;
    unsigned int* cmp1 = cmp0 + NI;
    int tot0 = 0, tot1 = 0;
#pragma unroll
    for (int pp = 0; pp < 2; pp++) {
        int pv = pp ? p1 : p0;
        if (pv >= NP) continue;
        float4 rA = pp ? r0b : r0a, rB = pp ? r1b : r1a;
        int4   mA = pp ? m0b : m0a, mB = pp ? m1b : m1a;
        float rv[8] = {rA.x, rA.y, rA.z, rA.w, rB.x, rB.y, rB.z, rB.w};
        int   mv[8] = {mA.x, mA.y, mA.z, mA.w, mB.x, mB.y, mB.z, mB.w};
        int cnt = 0;
#pragma unroll
        for (int j = 0; j < 8; j++) cnt += (mv[j] != 0);
        int off = cnt;
#pragma unroll
        for (int d = 1; d < 32; d <<= 1) {
            int t = __shfl_up_sync(0xffffffffu, off, d);
            if (lane >= d) off += t;
        }
        int tot = __shfl_sync(0xffffffffu, off, 31);
        off -= cnt;
        unsigned int* cc = pp ? cmp1 : cmp0;
        int pos = off;
#pragma unroll
        for (int j = 0; j < 8; j++) {
            if (mv[j]) {
                int b = __float2int_rn(rv[j] * (float)NBINS);
                if (b < 0) b = 0;
                if (b > NBINS) b = NBINS;
                cc[pos++] = (unsigned int)(b << 7);
            }
        }
        if (pp) tot1 = tot; else tot0 = tot;
    }
    int tmax = max(tot0, tot1);
    int totalp = (tmax + 3) & ~3;
    for (int t = tot0 + lane; t < totalp; t += 32) cmp0[t] = PADOFF;
    for (int t = tot1 + lane; t < totalp; t += 32) cmp1[t] = PADOFF;
    __syncwarp();

    // wait for all 8 slices (expect_tx = full block); then cluster sync so
    // no CTA exits while its multicast to peers could still be in flight.
    mbar_wait(bar1);
    CLUSTER_SYNC();
    if (p0 >= NP) return;

    // ---- NN accumulate, both persons interleaved ----
    const char* tb = (const char*)sm + lane * 4;
    const uint4* c0 = (const uint4*)cmp0;
    const uint4* c1 = (const uint4*)cmp1;
    unsigned long long a0 = 0ull, a1 = 0ull, a2 = 0ull, a3 = 0ull;
    const int n4 = totalp >> 2;
#pragma unroll 2
    for (int i = 0; i < n4; i++) {
        uint4 oA = c0[i];
        uint4 oB = c1[i];
        unsigned int vA0 = *(const unsigned int*)(tb + oA.x);
        unsigned int vA1 = *(const unsigned int*)(tb + oA.y);
        unsigned int vA2 = *(const unsigned int*)(tb + oA.z);
        unsigned int vA3 = *(const unsigned int*)(tb + oA.w);
        unsigned int vB0 = *(const unsigned int*)(tb + oB.x);
        unsigned int vB1 = *(const unsigned int*)(tb + oB.y);
        unsigned int vB2 = *(const unsigned int*)(tb + oB.z);
        unsigned int vB3 = *(const unsigned int*)(tb + oB.w);
        addbf2(a0, vA0); addbf2(a1, vA1);
        addbf2(a2, vB0); addbf2(a3, vB1);
        addbf2(a0, vA2); addbf2(a1, vA3);
        addbf2(a2, vB2); addbf2(a3, vB3);
    }
    asm("add.rn.f32x2 %0, %0, %1;" : "+l"(a0) : "l"(a1));
    asm("add.rn.f32x2 %0, %0, %1;" : "+l"(a2) : "l"(a3));
    float h0x, h0y, h1x, h1y;
    asm("mov.b64 {%0, %1}, %2;" : "=f"(h0x), "=f"(h0y) : "l"(a0));
    asm("mov.b64 {%0, %1}, %2;" : "=f"(h1x), "=f"(h1y) : "l"(a2));
    float inv0 = 1.0f / fmaxf((float)tot0, 1.0f);
    float inv1 = 1.0f / fmaxf((float)tot1, 1.0f);

    const int d0 = lane * 2;
    float* buf0 = sm + BUF_OFF + (wid * 2) * NH;
    float* buf1 = buf0 + NH;
    buf0[d0] = h0x * inv0; buf0[d0 + 1] = h0y * inv0;
    buf1[d0] = h1x * inv1; buf1[d0 + 1] = h1y * inv1;
    __syncwarp();

    // ---- layer 3 (weights shared across both persons) ----
    const ulonglong2* hb0 = (const ulonglong2*)buf0;
    const ulonglong2* hb1 = (const ulonglong2*)buf1;
    const ulonglong2* wa3 = (const ulonglong2*)(sm + W3A_OFF + lane * WSTRIDE);
    const ulonglong2* wb3 = (const ulonglong2*)(sm + W3B_OFF + lane * WSTRIDE);
    unsigned long long zP0, zP1, zQ0, zQ1;
    {
        float bz = b3[d0], bz1 = b3[d0 + 1], zf = 0.0f;
        asm("mov.b64 %0, {%1, %2};" : "=l"(zP0) : "f"(bz),  "f"(zf));
        asm("mov.b64 %0, {%1, %2};" : "=l"(zP1) : "f"(bz1), "f"(zf));
        zQ0 = zP0; zQ1 = zP1;
    }
#pragma unroll
    for (int k4 = 0; k4 < NH / 4; k4++) {
        ulonglong2 hA = hb0[k4];
        ulonglong2 hB = hb1[k4];
        ulonglong2 wa = wa3[k4];
        ulonglong2 wb = wb3[k4];
        fma2(zP0, hA.x, wa.x); fma2(zP0, hA.y, wa.y);
        fma2(zP1, hA.x, wb.x); fma2(zP1, hA.y, wb.y);
        fma2(zQ0, hB.x, wa.x); fma2(zQ0, hB.y, wa.y);
        fma2(zQ1, hB.x, wb.x); fma2(zQ1, hB.y, wb.y);
    }
    float s0, s1, s2, s3;
    asm("mov.b64 {%0, %1}, %2;" : "=f"(s0), "=f"(s1) : "l"(zP0));
    asm("mov.b64 {%0, %1}, %2;" : "=f"(s2), "=f"(s3) : "l"(zP1));
    float uA0 = elu_fast(s0 + s1), uA1 = elu_fast(s2 + s3);
    asm("mov.b64 {%0, %1}, %2;" : "=f"(s0), "=f"(s1) : "l"(zQ0));
    asm("mov.b64 {%0, %1}, %2;" : "=f"(s2), "=f"(s3) : "l"(zQ1));
    float uB0 = elu_fast(s0 + s1), uB1 = elu_fast(s2 + s3);
    __syncwarp();
    buf0[d0] = uA0; buf0[d0 + 1] = uA1;
    buf1[d0] = uB0; buf1[d0 + 1] = uB1;
    __syncwarp();

    // ---- layer 4 ----
    const ulonglong2* wa4 = (const ulonglong2*)(sm + W4A_OFF + lane * WSTRIDE);
    const ulonglong2* wb4 = (const ulonglong2*)(sm + W4B_OFF + lane * WSTRIDE);
    {
        float bz = b4[d0], bz1 = b4[d0 + 1], zf = 0.0f;
        asm("mov.b64 %0, {%1, %2};" : "=l"(zP0) : "f"(bz),  "f"(zf));
        asm("mov.b64 %0, {%1, %2};" : "=l"(zP1) : "f"(bz1), "f"(zf));
        zQ0 = zP0; zQ1 = zP1;
    }
#pragma unroll
    for (int k4 = 0; k4 < NH / 4; k4++) {
        ulonglong2 hA = hb0[k4];
        ulonglong2 hB = hb1[k4];
        ulonglong2 wa = wa4[k4];
        ulonglong2 wb = wb4[k4];
        fma2(zP0, hA.x, wa.x); fma2(zP0, hA.y, wa.y);
        fma2(zP1, hA.x, wb.x); fma2(zP1, hA.y, wb.y);
        fma2(zQ0, hB.x, wa.x); fma2(zQ0, hB.y, wa.y);
        fma2(zQ1, hB.x, wb.x); fma2(zQ1, hB.y, wb.y);
    }
    float oA0, oA1, oB0, oB1;
    asm("mov.b64 {%0, %1}, %2;" : "=f"(s0), "=f"(s1) : "l"(zP0));
    asm("mov.b64 {%0, %1}, %2;" : "=f"(s2), "=f"(s3) : "l"(zP1));
    oA0 = s0 + s1; oA1 = s2 + s3;
    asm("mov.b64 {%0, %1}, %2;" : "=f"(s0), "=f"(s1) : "l"(zQ0));
    asm("mov.b64 {%0, %1}, %2;" : "=f"(s2), "=f"(s3) : "l"(zQ1));
    oB0 = s0 + s1; oB1 = s2 + s3;

    // ---- epilogue per person ----
#pragma unroll
    for (int pp = 0; pp < 2; pp++) {
        int p = pp ? p1 : p0;
        if (p >= NP) break;
        float o0 = pp ? oB0 : oA0;
        float o1 = pp ? oB1 : oA1;
        float2 ov = make_float2(o0, o1);
        if (lane < 16) *(float2*)&out[O_AMU + p * NA + d0] = ov;
        else           *(float2*)&out[O_ALV + p * NA + (d0 - NA)] = ov;

        float lv0 = __shfl_down_sync(0xffffffffu, o0, 16);
        float lv1 = __shfl_down_sync(0xffffffffu, o1, 16);
        float term = 0.0f;
        if (lane < 16) {
            float2 eps = *(const float2*)&eps_ability[p * NA + d0];
            term = o0 + eps.x * __expf(0.5f * lv0)
                 + o1 + eps.y * __expf(0.5f * lv1);
        }
#pragma unroll
        for (int w = 16; w > 0; w >>= 1)
            term += __shfl_xor_sync(0xffffffffu, term, w);
        float asum = term;

        const float4* ifp = (const float4*)(sm + IFE_OFF + lane * 8);
        float4* orow = (float4*)(out + p * NI + lane * 8);
#pragma unroll
        for (int v = 0; v < 2; v++) {
            float4 f = ifp[v];
            float4 r;
            r.x = __fdividef(1.0f, 1.0f + __expf(-(asum + f.x)));
            r.y = __fdividef(1.0f, 1.0f + __expf(-(asum + f.y)));
            r.z = __fdividef(1.0f, 1.0f + __expf(-(asum + f.z)));
            r.w = __fdividef(1.0f, 1.0f + __expf(-(asum + f.w)));
            orow[v] = r;
        }
    }
}

// ---------------------------------------------------------------------------
extern "C" void kernel_launch(void* const* d_in, const int* in_sizes, int n_in,
                              void* d_out, int out_size) {
    const float* response     = (const float*)d_in[0];
    const int*   mask         = (const int*)  d_in[1];
    const int*   item_index   = (const int*)  d_in[2];
    const float* eps_ability  = (const float*)d_in[3];
    const float* eps_item     = (const float*)d_in[4];
    const float* w1           = (const float*)d_in[5];
    const float* b1           = (const float*)d_in[6];
    const float* w2           = (const float*)d_in[7];
    const float* b2           = (const float*)d_in[8];
    const float* w3           = (const float*)d_in[9];
    const float* b3           = (const float*)d_in[10];
    const float* w4           = (const float*)d_in[11];
    const float* b4           = (const float*)d_in[12];
    const float* mu_table     = (const float*)d_in[13];
    const float* logvar_table = (const float*)d_in[14];
    float* out = (float*)d_out;

    cudaFuncSetAttribute(vibo_main_kernel,
                         cudaFuncAttributeMaxDynamicSharedMemorySize, SMEM_BYTES);

    build_all_kernel<<<TROWS + 5, NH>>>(w1, b1, w2, b2, w3, w4,
                                        item_index, eps_item,
                                        mu_table, logvar_table, out);

    cudaLaunchConfig_t cfg = {};
    cfg.gridDim  = dim3(GRID, 1, 1);
    cfg.blockDim = dim3(NTHR, 1, 1);
    cfg.dynamicSmemBytes = SMEM_BYTES;
    cudaLaunchAttribute attrs[1];
    attrs[0].id = cudaLaunchAttributeClusterDimension;
    attrs[0].val.clusterDim = {CLUSTER, 1, 1};
    cfg.attrs = attrs;
    cfg.numAttrs = 1;
    cudaLaunchKernelEx(&cfg, vibo_main_kernel,
                       response, mask, eps_ability, b3, b4, out);
}

// round 13
// speedup vs baseline: 1.3919x; 1.3919x over previous
#include <cuda_runtime.h>
#include <math.h>

#define NP 4096
#define NI 256
#define NH 64
#define NA 32

#define NBINS 512
#define TROWS (NBINS + 1)        // rows 0..512
#define PADOFF (TROWS * 128)     // byte offset of zero row

#define WPC 28                   // persons per CTA (2 per warp)
#define NWARP 14
#define NTHR (NWARP * 32)        // 448
#define GRID ((NP + WPC - 1) / WPC)   // 147

// Output layout (flattened tuple, fp32)
#define O_AMU  (NP * NI)
#define O_ALV  (O_AMU + NP * NA)
#define O_IMU  (O_ALV + NP * NA)
#define O_ILV  (O_IMU + NI)

// ---- staged block (word offsets) ----
#define TAB_WORDS ((TROWS + 1) * 32)      // 16448 (incl zero row)
#define TAB_BYTES (TAB_WORDS * 4)         // 65792
#define WSTRIDE 68
#define W3A_OFF TAB_WORDS
#define W3B_OFF (W3A_OFF + 32 * WSTRIDE)
#define W4A_OFF (W3B_OFF + 32 * WSTRIDE)
#define W4B_OFF (W4A_OFF + 32 * WSTRIDE)
#define IFE_OFF (W4B_OFF + 32 * WSTRIDE)
#define STAGED_WORDS (IFE_OFF + NI)       // 25408
#define STAGED_BYTES (STAGED_WORDS * 4)   // 101632
#define CHUNK2_BYTES (STAGED_BYTES - TAB_BYTES)

// smem: staged | cmp[WPC][264] (4-entry pad for prefetch) | buf[WPC][64] | 2 mbars
#define CMP_STRIDE 264
#define CMP_OFF  STAGED_WORDS
#define BUF_OFF  (CMP_OFF + WPC * CMP_STRIDE)
#define MBAR_OFF (BUF_OFF + WPC * NH)
#define SMEM_BYTES (MBAR_OFF * 4 + 32)

__device__ __align__(16) float g_staged[STAGED_WORDS];

__device__ __forceinline__ float elu_ref(float x) {
    return x > 0.0f ? x : expm1f(x);
}
__device__ __forceinline__ float elu_fast(float x) {
    return x > 0.0f ? x : (__expf(x) - 1.0f);
}
__device__ __forceinline__ void addbf2(unsigned long long& acc, unsigned int w) {
    asm("{\n\t"
        ".reg .b32 lo, hi;\n\t"
        ".reg .b64 t;\n\t"
        "shl.b32 lo, %1, 16;\n\t"
        "and.b32 hi, %1, 0xffff0000;\n\t"
        "mov.b64 t, {lo, hi};\n\t"
        "add.rn.f32x2 %0, %0, t;\n\t"
        "}" : "+l"(acc) : "r"(w));
}
__device__ __forceinline__ void fma2(unsigned long long& acc,
                                     unsigned long long a, unsigned long long b) {
    asm("fma.rn.f32x2 %0, %1, %2, %0;" : "+l"(acc) : "l"(a), "l"(b));
}
__device__ __forceinline__ void mbar_wait(unsigned int mbar) {
    unsigned int done;
    asm volatile(
        "{\n\t.reg .pred p;\n\t"
        "mbarrier.try_wait.parity.acquire.cta.shared::cta.b64 p, [%1], 0;\n\t"
        "selp.b32 %0, 1, 0, p;\n\t}"
        : "=r"(done) : "r"(mbar) : "memory");
    while (!done) {
        asm volatile(
            "{\n\t.reg .pred p;\n\t"
            "mbarrier.try_wait.parity.acquire.cta.shared::cta.b64 p, [%1], 0, 0x989680;\n\t"
            "selp.b32 %0, 1, 0, p;\n\t}"
            : "=r"(done) : "r"(mbar) : "memory");
    }
}

// ---------------------------------------------------------------------------
// Kernel 1: FAST builder. 129 table blocks x 256 threads; w2 staged in smem
// once per block; one table entry per thread (4 rows x 64 dims).
// ---------------------------------------------------------------------------
#define TBLK ((TROWS + 3) / 4)   // 129

__global__ void build_all_kernel(const float* __restrict__ w1,
                                 const float* __restrict__ b1,
                                 const float* __restrict__ w2,
                                 const float* __restrict__ b2,
                                 const float* __restrict__ w3,
                                 const float* __restrict__ w4,
                                 const int*   __restrict__ item_index,
                                 const float* __restrict__ eps_item,
                                 const float* __restrict__ mu_table,
                                 const float* __restrict__ logvar_table,
                                 float* __restrict__ out) {
    int blk = blockIdx.x;
    int t = threadIdx.x;   // 0..255

    if (blk < TBLK) {
        __shared__ float w2s[NH * NH];
        __shared__ float sh1[4][NH];
        // stage w2 once (vectorized)
        {
            const float4* src = (const float4*)w2;
            float4* dst = (float4*)w2s;
#pragma unroll
            for (int i = t; i < (NH * NH) / 4; i += 256) dst[i] = src[i];
        }
        const int r = t >> 6;          // row-in-block 0..3
        const int j = t & 63;          // dim
        const int row = blk * 4 + r;
        {
            float x = (float)row * (1.0f / (float)NBINS);
            sh1[r][j] = elu_ref(fmaf(w1[j], x, b1[j]));
        }
        __syncthreads();
        if (row < TROWS) {
            float z0 = b2[j], z1 = 0.0f, z2 = 0.0f, z3 = 0.0f;
            const float* h1r = sh1[r];
#pragma unroll
            for (int k = 0; k < NH; k += 4) {
                z0 = fmaf(h1r[k],     w2s[k * NH + j],       z0);
                z1 = fmaf(h1r[k + 1], w2s[(k + 1) * NH + j], z1);
                z2 = fmaf(h1r[k + 2], w2s[(k + 2) * NH + j], z2);
                z3 = fmaf(h1r[k + 3], w2s[(k + 3) * NH + j], z3);
            }
            float z = elu_ref((z0 + z1) + (z2 + z3));
            float zo = __shfl_xor_sync(0xffffffffu, z, 1);
            if ((j & 1) == 0) {
                unsigned int u;
                asm("cvt.rn.bf16x2.f32 %0, %1, %2;" : "=r"(u) : "f"(zo), "f"(z));
                g_staged[row * 32 + (j >> 1)] = __uint_as_float(u);
            }
        }
    } else if (blk < TBLK + 4) {
        int arr = blk - TBLK;                  // 0:w3A 1:w3B 2:w4A 3:w4B
        const float* src = (arr < 2) ? w3 : w4;
        int parity = arr & 1;
        int dst = W3A_OFF + arr * 32 * WSTRIDE;
#pragma unroll
        for (int i = t; i < 32 * NH; i += 256) {
            int k = i >> 5, l = i & 31;
            g_staged[dst + l * WSTRIDE + k] = src[k * NH + 2 * l + parity];
        }
    } else {
        if (t < 32) g_staged[TROWS * 32 + t] = 0.0f;   // zero row
        if (t < NI) {
            int idx = item_index[t];
            float imu = mu_table[idx];
            float ilv = logvar_table[idx];
            g_staged[IFE_OFF + t] = fmaf(eps_item[t], __expf(0.5f * ilv), imu);
            out[O_IMU + t] = imu;
            out[O_ILV + t] = ilv;
        }
    }
}

// ---------------------------------------------------------------------------
// Kernel 2: 14 warps, 2 persons/warp, 1 CTA/SM. Split TMA prologue.
// Software-pipelined NN loop (offset prefetch).
// ---------------------------------------------------------------------------
__global__ __launch_bounds__(NTHR, 1)
void vibo_main_kernel(const float* __restrict__ response,
                      const int*   __restrict__ mask,
                      const float* __restrict__ eps_ability,
                      const float* __restrict__ b3,
                      const float* __restrict__ b4,
                      float* __restrict__ out) {
    extern __shared__ float sm[];
    const int tid = threadIdx.x;
    const int wid  = tid >> 5;
    const int lane = tid & 31;
    const int p0 = blockIdx.x * WPC + wid * 2;
    const int p1 = p0 + 1;

    unsigned int smb;
    asm("{ .reg .u64 t; cvta.to.shared.u64 t, %1; cvt.u32.u64 %0, t; }"
        : "=r"(smb) : "l"(sm));
    const unsigned int bar1 = smb + MBAR_OFF * 4;
    const unsigned int bar2 = bar1 + 8;

    // ---- early gmem loads (both persons) ----
    float4 r0a, r1a, r0b, r1b; int4 m0a, m1a, m0b, m1b;
    if (p0 < NP) {
        const float4* rp = (const float4*)(response + p0 * NI);
        const int4*   mp = (const int4*)(mask + p0 * NI);
        r0a = rp[lane * 2]; r1a = rp[lane * 2 + 1];
        m0a = mp[lane * 2]; m1a = mp[lane * 2 + 1];
    }
    if (p1 < NP) {
        const float4* rp = (const float4*)(response + p1 * NI);
        const int4*   mp = (const int4*)(mask + p1 * NI);
        r0b = rp[lane * 2]; r1b = rp[lane * 2 + 1];
        m0b = mp[lane * 2]; m1b = mp[lane * 2 + 1];
    }

    if (tid == 0) {
        asm volatile("mbarrier.init.shared.b64 [%0], 1;" :: "r"(bar1) : "memory");
        asm volatile("mbarrier.init.shared.b64 [%0], 1;" :: "r"(bar2) : "memory");
    }
    __syncthreads();
    if (tid == 0) {
        asm volatile("mbarrier.arrive.expect_tx.shared.b64 _, [%0], %1;"
                     :: "r"(bar1), "r"((unsigned)TAB_BYTES) : "memory");
        asm volatile("cp.async.bulk.shared::cluster.global.mbarrier::complete_tx::bytes "
                     "[%0], [%1], %2, [%3];"
                     :: "r"(smb), "l"((const void*)g_staged),
                        "r"((unsigned)TAB_BYTES), "r"(bar1) : "memory");
        asm volatile("mbarrier.arrive.expect_tx.shared.b64 _, [%0], %1;"
                     :: "r"(bar2), "r"((unsigned)CHUNK2_BYTES) : "memory");
        asm volatile("cp.async.bulk.shared::cluster.global.mbarrier::complete_tx::bytes "
                     "[%0], [%1], %2, [%3];"
                     :: "r"(smb + TAB_BYTES), "l"((const void*)(g_staged + TAB_WORDS)),
                        "r"((unsigned)CHUNK2_BYTES), "r"(bar2) : "memory");
    }

    // ---- compaction for both persons (overlaps TMA) ----
    unsigned int* cmp0 = (unsigned int*)(sm + CMP_OFF) + (wid * 2) * CMP_STRIDE;
    unsigned int* cmp1 = cmp0 + CMP_STRIDE;
    int tot0 = 0, tot1 = 0;
#pragma unroll
    for (int pp = 0; pp < 2; pp++) {
        int pv = pp ? p1 : p0;
        if (pv >= NP) continue;
        float4 rA = pp ? r0b : r0a, rB = pp ? r1b : r1a;
        int4   mA = pp ? m0b : m0a, mB = pp ? m1b : m1a;
        float rv[8] = {rA.x, rA.y, rA.z, rA.w, rB.x, rB.y, rB.z, rB.w};
        int   mv[8] = {mA.x, mA.y, mA.z, mA.w, mB.x, mB.y, mB.z, mB.w};
        int cnt = 0;
#pragma unroll
        for (int j = 0; j < 8; j++) cnt += (mv[j] != 0);
        int off = cnt;
#pragma unroll
        for (int d = 1; d < 32; d <<= 1) {
            int t = __shfl_up_sync(0xffffffffu, off, d);
            if (lane >= d) off += t;
        }
        int tot = __shfl_sync(0xffffffffu, off, 31);
        off -= cnt;
        unsigned int* cc = pp ? cmp1 : cmp0;
        int pos = off;
#pragma unroll
        for (int j = 0; j < 8; j++) {
            if (mv[j]) {
                int b = __float2int_rn(rv[j] * (float)NBINS);
                if (b < 0) b = 0;
                if (b > NBINS) b = NBINS;
                cc[pos++] = (unsigned int)(b << 7);
            }
        }
        if (pp) tot1 = tot; else tot0 = tot;
    }
    // pad to common multiple-of-4 length, +4 extra for prefetch safety
    int tmax = max(tot0, tot1);
    int totalp = (tmax + 3) & ~3;
    for (int t = tot0 + lane; t < totalp + 4; t += 32) cmp0[t] = PADOFF;
    for (int t = tot1 + lane; t < totalp + 4; t += 32) cmp1[t] = PADOFF;
    __syncwarp();

    mbar_wait(bar1);
    if (p0 >= NP) return;

    // ---- NN accumulate, both persons, prefetched offsets ----
    const char* tb = (const char*)sm + lane * 4;
    const uint4* c0 = (const uint4*)cmp0;
    const uint4* c1 = (const uint4*)cmp1;
    unsigned long long a0 = 0ull, a1 = 0ull, a2 = 0ull, a3 = 0ull;
    const int n4 = totalp >> 2;
    uint4 oA = c0[0];
    uint4 oB = c1[0];
#pragma unroll 2
    for (int i = 0; i < n4; i++) {
        uint4 nA = c0[i + 1];     // padded: always safe
        uint4 nB = c1[i + 1];
        unsigned int vA0 = *(const unsigned int*)(tb + oA.x);
        unsigned int vA1 = *(const unsigned int*)(tb + oA.y);
        unsigned int vA2 = *(const unsigned int*)(tb + oA.z);
        unsigned int vA3 = *(const unsigned int*)(tb + oA.w);
        unsigned int vB0 = *(const unsigned int*)(tb + oB.x);
        unsigned int vB1 = *(const unsigned int*)(tb + oB.y);
        unsigned int vB2 = *(const unsigned int*)(tb + oB.z);
        unsigned int vB3 = *(const unsigned int*)(tb + oB.w);
        addbf2(a0, vA0); addbf2(a1, vA1);
        addbf2(a2, vB0); addbf2(a3, vB1);
        addbf2(a0, vA2); addbf2(a1, vA3);
        addbf2(a2, vB2); addbf2(a3, vB3);
        oA = nA; oB = nB;
    }
    asm("add.rn.f32x2 %0, %0, %1;" : "+l"(a0) : "l"(a1));
    asm("add.rn.f32x2 %0, %0, %1;" : "+l"(a2) : "l"(a3));
    float h0x, h0y, h1x, h1y;
    asm("mov.b64 {%0, %1}, %2;" : "=f"(h0x), "=f"(h0y) : "l"(a0));
    asm("mov.b64 {%0, %1}, %2;" : "=f"(h1x), "=f"(h1y) : "l"(a2));
    float inv0 = 1.0f / fmaxf((float)tot0, 1.0f);
    float inv1 = 1.0f / fmaxf((float)tot1, 1.0f);

    const int d0 = lane * 2;
    float* buf0 = sm + BUF_OFF + (wid * 2) * NH;
    float* buf1 = buf0 + NH;
    buf0[d0] = h0x * inv0; buf0[d0 + 1] = h0y * inv0;
    buf1[d0] = h1x * inv1; buf1[d0 + 1] = h1y * inv1;
    __syncwarp();

    mbar_wait(bar2);

    // ---- layer 3 (weights shared across both persons) ----
    const ulonglong2* hb0 = (const ulonglong2*)buf0;
    const ulonglong2* hb1 = (const ulonglong2*)buf1;
    const ulonglong2* wa3 = (const ulonglong2*)(sm + W3A_OFF + lane * WSTRIDE);
    const ulonglong2* wb3 = (const ulonglong2*)(sm + W3B_OFF + lane * WSTRIDE);
    unsigned long long zP0, zP1, zQ0, zQ1;
    {
        float bz = b3[d0], bz1 = b3[d0 + 1], zf = 0.0f;
        asm("mov.b64 %0, {%1, %2};" : "=l"(zP0) : "f"(bz),  "f"(zf));
        asm("mov.b64 %0, {%1, %2};" : "=l"(zP1) : "f"(bz1), "f"(zf));
        zQ0 = zP0; zQ1 = zP1;
    }
#pragma unroll
    for (int k4 = 0; k4 < NH / 4; k4++) {
        ulonglong2 hA = hb0[k4];
        ulonglong2 hB = hb1[k4];
        ulonglong2 wa = wa3[k4];
        ulonglong2 wb = wb3[k4];
        fma2(zP0, hA.x, wa.x); fma2(zP0, hA.y, wa.y);
        fma2(zP1, hA.x, wb.x); fma2(zP1, hA.y, wb.y);
        fma2(zQ0, hB.x, wa.x); fma2(zQ0, hB.y, wa.y);
        fma2(zQ1, hB.x, wb.x); fma2(zQ1, hB.y, wb.y);
    }
    float s0, s1, s2, s3;
    asm("mov.b64 {%0, %1}, %2;" : "=f"(s0), "=f"(s1) : "l"(zP0));
    asm("mov.b64 {%0, %1}, %2;" : "=f"(s2), "=f"(s3) : "l"(zP1));
    float uA0 = elu_fast(s0 + s1), uA1 = elu_fast(s2 + s3);
    asm("mov.b64 {%0, %1}, %2;" : "=f"(s0), "=f"(s1) : "l"(zQ0));
    asm("mov.b64 {%0, %1}, %2;" : "=f"(s2), "=f"(s3) : "l"(zQ1));
    float uB0 = elu_fast(s0 + s1), uB1 = elu_fast(s2 + s3);
    __syncwarp();
    buf0[d0] = uA0; buf0[d0 + 1] = uA1;
    buf1[d0] = uB0; buf1[d0 + 1] = uB1;
    __syncwarp();

    // ---- layer 4 ----
    const ulonglong2* wa4 = (const ulonglong2*)(sm + W4A_OFF + lane * WSTRIDE);
    const ulonglong2* wb4 = (const ulonglong2*)(sm + W4B_OFF + lane * WSTRIDE);
    {
        float bz = b4[d0], bz1 = b4[d0 + 1], zf = 0.0f;
        asm("mov.b64 %0, {%1, %2};" : "=l"(zP0) : "f"(bz),  "f"(zf));
        asm("mov.b64 %0, {%1, %2};" : "=l"(zP1) : "f"(bz1), "f"(zf));
        zQ0 = zP0; zQ1 = zP1;
    }
#pragma unroll
    for (int k4 = 0; k4 < NH / 4; k4++) {
        ulonglong2 hA = hb0[k4];
        ulonglong2 hB = hb1[k4];
        ulonglong2 wa = wa4[k4];
        ulonglong2 wb = wb4[k4];
        fma2(zP0, hA.x, wa.x); fma2(zP0, hA.y, wa.y);
        fma2(zP1, hA.x, wb.x); fma2(zP1, hA.y, wb.y);
        fma2(zQ0, hB.x, wa.x); fma2(zQ0, hB.y, wa.y);
        fma2(zQ1, hB.x, wb.x); fma2(zQ1, hB.y, wb.y);
    }
    float oA0, oA1, oB0, oB1;
    asm("mov.b64 {%0, %1}, %2;" : "=f"(s0), "=f"(s1) : "l"(zP0));
    asm("mov.b64 {%0, %1}, %2;" : "=f"(s2), "=f"(s3) : "l"(zP1));
    oA0 = s0 + s1; oA1 = s2 + s3;
    asm("mov.b64 {%0, %1}, %2;" : "=f"(s0), "=f"(s1) : "l"(zQ0));
    asm("mov.b64 {%0, %1}, %2;" : "=f"(s2), "=f"(s3) : "l"(zQ1));
    oB0 = s0 + s1; oB1 = s2 + s3;

    // ---- epilogue per person ----
#pragma unroll
    for (int pp = 0; pp < 2; pp++) {
        int p = pp ? p1 : p0;
        if (p >= NP) break;
        float o0 = pp ? oB0 : oA0;
        float o1 = pp ? oB1 : oA1;
        float2 ov = make_float2(o0, o1);
        if (lane < 16) *(float2*)&out[O_AMU + p * NA + d0] = ov;
        else           *(float2*)&out[O_ALV + p * NA + (d0 - NA)] = ov;

        float lv0 = __shfl_down_sync(0xffffffffu, o0, 16);
        float lv1 = __shfl_down_sync(0xffffffffu, o1, 16);
        float term = 0.0f;
        if (lane < 16) {
            float2 eps = *(const float2*)&eps_ability[p * NA + d0];
            term = o0 + eps.x * __expf(0.5f * lv0)
                 + o1 + eps.y * __expf(0.5f * lv1);
        }
#pragma unroll
        for (int w = 16; w > 0; w >>= 1)
            term += __shfl_xor_sync(0xffffffffu, term, w);
        float asum = term;

        const float4* ifp = (const float4*)(sm + IFE_OFF + lane * 8);
        float4* orow = (float4*)(out + p * NI + lane * 8);
#pragma unroll
        for (int v = 0; v < 2; v++) {
            float4 f = ifp[v];
            float4 r;
            r.x = __fdividef(1.0f, 1.0f + __expf(-(asum + f.x)));
            r.y = __fdividef(1.0f, 1.0f + __expf(-(asum + f.y)));
            r.z = __fdividef(1.0f, 1.0f + __expf(-(asum + f.z)));
            r.w = __fdividef(1.0f, 1.0f + __expf(-(asum + f.w)));
            orow[v] = r;
        }
    }
}

// ---------------------------------------------------------------------------
extern "C" void kernel_launch(void* const* d_in, const int* in_sizes, int n_in,
                              void* d_out, int out_size) {
    const float* response     = (const float*)d_in[0];
    const int*   mask         = (const int*)  d_in[1];
    const int*   item_index   = (const int*)  d_in[2];
    const float* eps_ability  = (const float*)d_in[3];
    const float* eps_item     = (const float*)d_in[4];
    const float* w1           = (const float*)d_in[5];
    const float* b1           = (const float*)d_in[6];
    const float* w2           = (const float*)d_in[7];
    const float* b2           = (const float*)d_in[8];
    const float* w3           = (const float*)d_in[9];
    const float* b3           = (const float*)d_in[10];
    const float* w4           = (const float*)d_in[11];
    const float* b4           = (const float*)d_in[12];
    const float* mu_table     = (const float*)d_in[13];
    const float* logvar_table = (const float*)d_in[14];
    float* out = (float*)d_out;

    cudaFuncSetAttribute(vibo_main_kernel,
                         cudaFuncAttributeMaxDynamicSharedMemorySize, SMEM_BYTES);

    build_all_kernel<<<TBLK + 5, 256>>>(w1, b1, w2, b2, w3, w4,
                                        item_index, eps_item,
                                        mu_table, logvar_table, out);

    vibo_main_kernel<<<GRID, NTHR, SMEM_BYTES>>>(response, mask,
                                                 eps_ability, b3, b4, out);
}